// round 6
// baseline (speedup 1.0000x reference)
#include <cuda_runtime.h>

#define NPTS 65536
#define NCH 76          // 4*19
#define NF 64
#define CAP 65536       // per-feature candidate cap == NPTS: overflow impossible
#define NSAMP 4096
#define KGUAR 32        // threshold = exact 32nd-largest sample value
#define NPACKBLK (NCH * NPTS / 128)   // 38912
#define NCOLBLK (NPTS / 128)          // 512

typedef unsigned long long u64;

__device__ unsigned g_maskT[2048 * NCH];     // [word_in_ch][ch] transposed
__device__ int      g_popcnt[NCH];
__device__ float    g_zres[NCH * NF];
__device__ float    g_zf[NF];                // zero-point fallback feature
__device__ float    g_sfeat[NSAMP * NF];     // sample features [s][f]
__device__ float    g_T[NF];                 // per-feature candidate threshold
__device__ int      g_cnt[NF];
__device__ int2     g_cand[(size_t)NF * CAP];       // (.x = point idx, .y = float bits)
__device__ float    g_feats[(size_t)NPTS * NF];     // [n][f] full features (fallback)

__device__ __forceinline__ float lrelu(float a) { return fmaxf(a, 0.01f * a); }

__device__ __forceinline__ unsigned okey(float f) {
    unsigned u = __float_as_uint(f);
    return u ^ (unsigned)(((int)u >> 31) | (int)0x80000000);
}
__device__ __forceinline__ float dekey(unsigned k) {
    unsigned u = (k & 0x80000000u) ? (k ^ 0x80000000u) : ~k;
    return __uint_as_float(u);
}

// ---- packed f32x2 helpers (sm_100+) ----
__device__ __forceinline__ u64 pk(float lo, float hi) {
    u64 r; asm("mov.b64 %0, {%1,%2};" : "=l"(r) : "f"(lo), "f"(hi)); return r;
}
__device__ __forceinline__ void unpk(u64 a, float& lo, float& hi) {
    asm("mov.b64 {%0,%1}, %2;" : "=f"(lo), "=f"(hi) : "l"(a));
}
__device__ __forceinline__ u64 ffma2(u64 a, u64 b, u64 c) {
    u64 d; asm("fma.rn.f32x2 %0, %1, %2, %3;" : "=l"(d) : "l"(a), "l"(b), "l"(c));
    return d;
}

// ---- shared-memory weight loader ----
__device__ __forceinline__ void load_mlp_smem(
    const float* w1, const float* b1, const float* w2, const float* b2,
    const float* w3, const float* b3,
    float* sw1, float* sb1, u64* sw2q, float* sb2, u64* sw3q, float* sb3,
    int tid, int nt)
{
    for (int i = tid; i < 128; i += nt) sw1[i] = w1[i];
    for (int i = tid; i < 64; i += nt) { sb1[i] = b1[i]; sb2[i] = b2[i]; sb3[i] = b3[i]; }
    for (int i = tid; i < 2048; i += nt) {
        sw2q[i] = ((const u64*)w2)[i];
        sw3q[i] = ((const u64*)w3)[i];
    }
}

// ---- full 3-layer MLP for one point (weights in smem) ----
__device__ __forceinline__ void mlp_point(
    float uu, float vv,
    const float* sw1, const float* sb1,
    const u64* sw2q, const float* sb2,
    const u64* sw3q, const float* sb3,
    float zs[64])
{
    u64 zq[32];
#pragma unroll
    for (int k = 0; k < 32; k++) {
        float a0 = fmaf(sw1[4 * k + 0], uu, fmaf(sw1[4 * k + 1], vv, sb1[2 * k]));
        float a1 = fmaf(sw1[4 * k + 2], uu, fmaf(sw1[4 * k + 3], vv, sb1[2 * k + 1]));
        zq[k] = pk(lrelu(a0), lrelu(a1));
    }
    float zt[64];
#pragma unroll
    for (int k = 0; k < 64; k++) {
        const ulonglong2* wr = (const ulonglong2*)(sw2q + k * 32);
        u64 a0 = 0ull, a1 = 0ull;
#pragma unroll
        for (int j2 = 0; j2 < 16; j2++) {
            ulonglong2 wv = wr[j2];
            a0 = ffma2(wv.x, zq[2 * j2 + 0], a0);
            a1 = ffma2(wv.y, zq[2 * j2 + 1], a1);
        }
        float l0, h0, l1, h1;
        unpk(a0, l0, h0); unpk(a1, l1, h1);
        zt[k] = lrelu((l0 + h0) + (l1 + h1) + sb2[k]);
    }
#pragma unroll
    for (int k = 0; k < 32; k++) zq[k] = pk(zt[2 * k], zt[2 * k + 1]);
#pragma unroll
    for (int k = 0; k < 64; k++) {
        const ulonglong2* wr = (const ulonglong2*)(sw3q + k * 32);
        u64 a0 = 0ull, a1 = 0ull;
#pragma unroll
        for (int j2 = 0; j2 < 16; j2++) {
            ulonglong2 wv = wr[j2];
            a0 = ffma2(wv.x, zq[2 * j2 + 0], a0);
            a1 = ffma2(wv.y, zq[2 * j2 + 1], a1);
        }
        float l0, h0, l1, h1;
        unpk(a0, l0, h0); unpk(a1, l1, h1);
        zs[k] = lrelu((l0 + h0) + (l1 + h1) + sb3[k]);
    }
}

#define SIDX(s) (((s) * 9973) & 65535)

// ---------------- prep: blocks 0..31 sample MLP; block 32 zeros + zero-feat ----------------
__global__ __launch_bounds__(128) void k_prep(
    const float* __restrict__ grid,
    const float* __restrict__ w1, const float* __restrict__ b1,
    const float* __restrict__ w2, const float* __restrict__ b2,
    const float* __restrict__ w3, const float* __restrict__ b3)
{
    int tid = threadIdx.x;
    if (blockIdx.x == NSAMP / 128) {
        __shared__ float z1[64], z2[64];
        if (tid < NCH) g_popcnt[tid] = 0;
        if (tid < NF) g_cnt[tid] = 0;
        if (tid < 64) z1[tid] = lrelu(b1[tid]);
        __syncthreads();
        if (tid < 64) {
            float a = b2[tid];
            for (int j = 0; j < 64; j++) a += w2[tid * 64 + j] * z1[j];
            z2[tid] = lrelu(a);
        }
        __syncthreads();
        if (tid < 64) {
            float a = b3[tid];
            for (int j = 0; j < 64; j++) a += w3[tid * 64 + j] * z2[j];
            g_zf[tid] = lrelu(a);
        }
        return;
    }
    __shared__ float sw1[128], sb1[64], sb2[64], sb3[64];
    __shared__ u64 sw2q[2048], sw3q[2048];
    load_mlp_smem(w1, b1, w2, b2, w3, b3, sw1, sb1, sw2q, sb2, sw3q, sb3, tid, 128);
    __syncthreads();

    int s = blockIdx.x * 128 + tid;
    int n = SIDX(s);
    float zs[64];
    mlp_point(grid[n], grid[NPTS + n], sw1, sb1, sw2q, sb2, sw3q, sb3, zs);
    float4* op = (float4*)(g_sfeat + s * 64);
#pragma unroll
    for (int k = 0; k < 16; k++)
        op[k] = make_float4(zs[4 * k], zs[4 * k + 1], zs[4 * k + 2], zs[4 * k + 3]);
}

// ---------------- select: exact KGUAR-th largest of NSAMP samples per feature ----------------
__global__ __launch_bounds__(32) void k_select() {
    int f = blockIdx.x;
    int lane = threadIdx.x;
    unsigned keys[NSAMP / 32];
#pragma unroll
    for (int i = 0; i < NSAMP / 32; i++)
        keys[i] = okey(g_sfeat[(i * 32 + lane) * 64 + f]);

    // greedy MSB->LSB: largest T with count(keys >= T) >= KGUAR
    unsigned T = 0u;
#pragma unroll
    for (int bit = 31; bit >= 0; bit--) {
        unsigned cand = T | (1u << bit);
        int c = 0;
#pragma unroll
        for (int i = 0; i < NSAMP / 32; i++) c += (keys[i] >= cand);
        c += __shfl_xor_sync(0xffffffffu, c, 16);
        c += __shfl_xor_sync(0xffffffffu, c, 8);
        c += __shfl_xor_sync(0xffffffffu, c, 4);
        c += __shfl_xor_sync(0xffffffffu, c, 2);
        c += __shfl_xor_sync(0xffffffffu, c, 1);
        if (c >= KGUAR) T = cand;
    }
    if (lane == 0) g_T[f] = dekey(T);
}

// ---------------- fused: blocks [0,512) MLP+collect+store; rest pack masks ----------------
__global__ __launch_bounds__(128) void k_main(
    const int* __restrict__ x,
    const float* __restrict__ grid,
    const float* __restrict__ w1, const float* __restrict__ b1,
    const float* __restrict__ w2, const float* __restrict__ b2,
    const float* __restrict__ w3, const float* __restrict__ b3)
{
    __shared__ float sw1[128], sb1[64], sb2[64], sb3[64], sT[64];
    __shared__ u64 sw2q[2048], sw3q[2048];
    __shared__ int sp[4];

    int tid = threadIdx.x;

    if (blockIdx.x >= NCOLBLK) {
        // ---- pack masks ----
        int g = (blockIdx.x - NCOLBLK) * 128 + tid;   // < NCH*NPTS
        int ch = g >> 16;
        int pos = g & 65535;
        int v = (x[g] == 1);
        unsigned ball = __ballot_sync(0xffffffffu, v);
        int lane = tid & 31, wp = tid >> 5;
        if (lane == 0) {
            g_maskT[(pos >> 5) * NCH + ch] = ball;
            sp[wp] = __popc(ball);
        }
        __syncthreads();
        if (tid == 0)
            atomicAdd(&g_popcnt[ch], sp[0] + sp[1] + sp[2] + sp[3]);
        return;
    }

    // ---- collect ----
    load_mlp_smem(w1, b1, w2, b2, w3, b3, sw1, sb1, sw2q, sb2, sw3q, sb3, tid, 128);
    if (tid < 64) sT[tid] = g_T[tid];
    __syncthreads();

    int n = blockIdx.x * 128 + tid;
    float zs[64];
    mlp_point(grid[n], grid[NPTS + n], sw1, sb1, sw2q, sb2, sw3q, sb3, zs);

    float4* op = (float4*)(g_feats + (size_t)n * 64);
#pragma unroll
    for (int k = 0; k < 16; k++)
        op[k] = make_float4(zs[4 * k], zs[4 * k + 1], zs[4 * k + 2], zs[4 * k + 3]);

#pragma unroll
    for (int k = 0; k < 64; k++) {
        if (zs[k] >= sT[k]) {
            int p = atomicAdd(&g_cnt[k], 1);
            g_cand[(size_t)k * CAP + p] = make_int2(n, __float_as_int(zs[k]));
        }
    }
}

// ---------------- per-feature masked max over candidates (+ cheap exact fallback) ----------------
__global__ __launch_bounds__(128) void k_query() {
    __shared__ int s_nfb;
    __shared__ unsigned char sflag[NCH];
    __shared__ float sred[128];

    int tid = threadIdx.x;
    int f = blockIdx.x;
    int cnt = g_cnt[f];           // <= CAP by construction

    if (tid == 0) s_nfb = 0;
    if (tid < NCH) sflag[tid] = 0;
    __syncthreads();

    if (tid < NCH) {
        int ch = tid;
        if (g_popcnt[ch] > 0) {
            float m = -1e30f;
            bool found = false;
            const int2* cd = g_cand + (size_t)f * CAP;
            for (int i = 0; i < cnt; i++) {
                int2 c = __ldg(cd + i);
                unsigned w = __ldg(&g_maskT[(c.x >> 5) * NCH + ch]);
                if ((w >> (c.x & 31)) & 1) {
                    m = fmaxf(m, __int_as_float(c.y));
                    found = true;
                }
            }
            if (found) g_zres[ch * 64 + f] = m;
            else { sflag[ch] = 1; atomicAdd(&s_nfb, 1); }
        }
    }
    __syncthreads();
    if (s_nfb == 0) return;

    // exact fallback (P ~ 2^-32 per pair): dense scan of stored feature column
    for (int ch = 0; ch < NCH; ch++) {
        if (!sflag[ch]) continue;
        float m = -1e30f;
        for (int base = 0; base < NPTS; base += 128) {
            int n = base + tid;
            float v = __ldg(&g_feats[(size_t)n * 64 + f]);
            unsigned w = g_maskT[(n >> 5) * NCH + ch];
            if ((w >> (n & 31)) & 1) m = fmaxf(m, v);
        }
        sred[tid] = m;
        __syncthreads();
        for (int off = 64; off; off >>= 1) {
            if (tid < off) sred[tid] = fmaxf(sred[tid], sred[tid + off]);
            __syncthreads();
        }
        if (tid == 0) g_zres[ch * 64 + f] = sred[0];
        __syncthreads();
    }
}

// ---------------- final FC + repeat 18 ----------------
__global__ __launch_bounds__(128) void k_fc(const float* __restrict__ fcw,
                                            const float* __restrict__ fcb,
                                            float* __restrict__ out)
{
    __shared__ float fs[NCH * NF];
    __shared__ float rw[4][4];

    int tid = threadIdx.x;
    int o = blockIdx.x;
    for (int i = tid; i < NCH * NF; i += 128) {
        int ch = i >> 6;
        fs[i] = (g_popcnt[ch] > 0) ? g_zres[i] : g_zf[i & 63];
    }
    __syncthreads();

    float p0 = 0.f, p1 = 0.f, p2 = 0.f, p3 = 0.f;
    const float* wr = fcw + o * 1216;
    for (int k = tid; k < 1216; k += 128) {
        float w = wr[k];
        p0 += w * fs[k];
        p1 += w * fs[1216 + k];
        p2 += w * fs[2432 + k];
        p3 += w * fs[3648 + k];
    }
#pragma unroll
    for (int off = 16; off; off >>= 1) {
        p0 += __shfl_xor_sync(0xffffffffu, p0, off);
        p1 += __shfl_xor_sync(0xffffffffu, p1, off);
        p2 += __shfl_xor_sync(0xffffffffu, p2, off);
        p3 += __shfl_xor_sync(0xffffffffu, p3, off);
    }
    int lane = tid & 31, wp = tid >> 5;
    if (lane == 0) { rw[wp][0] = p0; rw[wp][1] = p1; rw[wp][2] = p2; rw[wp][3] = p3; }
    __syncthreads();
    if (tid < 4) {
        float s = rw[0][tid] + rw[1][tid] + rw[2][tid] + rw[3][tid];
        float scale = rsqrtf(1216.0f);
        float val = s * scale + fcb[o];
#pragma unroll
        for (int r = 0; r < 18; r++)
            out[(tid * 18 + r) * 512 + o] = val;
    }
}

extern "C" void kernel_launch(void* const* d_in, const int* in_sizes, int n_in,
                              void* d_out, int out_size) {
    const int*   x    = (const int*)d_in[0];
    const float* grid = (const float*)d_in[1];
    const float* w1   = (const float*)d_in[2];
    const float* b1   = (const float*)d_in[3];
    const float* w2   = (const float*)d_in[4];
    const float* b2   = (const float*)d_in[5];
    const float* w3   = (const float*)d_in[6];
    const float* b3   = (const float*)d_in[7];
    const float* fcw  = (const float*)d_in[8];
    const float* fcb  = (const float*)d_in[9];
    float* out = (float*)d_out;

    k_prep<<<NSAMP / 128 + 1, 128>>>(grid, w1, b1, w2, b2, w3, b3);
    k_select<<<NF, 32>>>();
    k_main<<<NCOLBLK + NPACKBLK, 128>>>(x, grid, w1, b1, w2, b2, w3, b3);
    k_query<<<NF, 128>>>();
    k_fc<<<512, 128>>>(fcw, fcb, out);
}

// round 7
// speedup vs baseline: 1.5044x; 1.5044x over previous
#include <cuda_runtime.h>

#define NPTS 65536
#define NCH 76          // 4*19
#define NF 64
#define CAP 65536       // per-feature candidate cap == NPTS: overflow impossible
#define NSAMP 4096
#define KGUAR 32        // threshold = exact 32nd-largest sample value
#define NPACKBLK (NCH * NPTS / 128)   // 38912
#define NCOLBLK (NPTS / 128)          // 512

typedef unsigned long long u64;

__device__ unsigned g_maskT[2048 * NCH];     // [word_in_ch][ch] transposed
__device__ int      g_popcnt[NCH];
__device__ float    g_zres[NCH * NF];
__device__ float    g_zf[NF];                // zero-point fallback feature
__device__ float    g_sfeat[NSAMP * NF];     // sample features [s][f]
__device__ float    g_T[NF];                 // per-feature candidate threshold
__device__ int      g_cnt[NF];
__device__ int2     g_cand[(size_t)NF * CAP];       // (.x = point idx, .y = float bits)
__device__ float    g_feats[(size_t)NPTS * NF];     // [n][f] full features (fallback)

__device__ __forceinline__ float lrelu(float a) { return fmaxf(a, 0.01f * a); }

__device__ __forceinline__ unsigned okey(float f) {
    unsigned u = __float_as_uint(f);
    return u ^ (unsigned)(((int)u >> 31) | (int)0x80000000);
}
__device__ __forceinline__ float dekey(unsigned k) {
    unsigned u = (k & 0x80000000u) ? (k ^ 0x80000000u) : ~k;
    return __uint_as_float(u);
}

// ---- packed f32x2 helpers (sm_100+) ----
__device__ __forceinline__ u64 pk(float lo, float hi) {
    u64 r; asm("mov.b64 %0, {%1,%2};" : "=l"(r) : "f"(lo), "f"(hi)); return r;
}
__device__ __forceinline__ void unpk(u64 a, float& lo, float& hi) {
    asm("mov.b64 {%0,%1}, %2;" : "=f"(lo), "=f"(hi) : "l"(a));
}
__device__ __forceinline__ u64 ffma2(u64 a, u64 b, u64 c) {
    u64 d; asm("fma.rn.f32x2 %0, %1, %2, %3;" : "=l"(d) : "l"(a), "l"(b), "l"(c));
    return d;
}

// ---- shared-memory weight loader ----
__device__ __forceinline__ void load_mlp_smem(
    const float* w1, const float* b1, const float* w2, const float* b2,
    const float* w3, const float* b3,
    float* sw1, float* sb1, u64* sw2q, float* sb2, u64* sw3q, float* sb3,
    int tid, int nt)
{
    for (int i = tid; i < 128; i += nt) sw1[i] = w1[i];
    for (int i = tid; i < 64; i += nt) { sb1[i] = b1[i]; sb2[i] = b2[i]; sb3[i] = b3[i]; }
    for (int i = tid; i < 2048; i += nt) {
        sw2q[i] = ((const u64*)w2)[i];
        sw3q[i] = ((const u64*)w3)[i];
    }
}

// ---- full 3-layer MLP for one point (weights in smem), 4 FFMA2 chains ----
__device__ __forceinline__ void mlp_point(
    float uu, float vv,
    const float* sw1, const float* sb1,
    const u64* sw2q, const float* sb2,
    const u64* sw3q, const float* sb3,
    float zs[64])
{
    u64 zq[32];
#pragma unroll
    for (int k = 0; k < 32; k++) {
        float a0 = fmaf(sw1[4 * k + 0], uu, fmaf(sw1[4 * k + 1], vv, sb1[2 * k]));
        float a1 = fmaf(sw1[4 * k + 2], uu, fmaf(sw1[4 * k + 3], vv, sb1[2 * k + 1]));
        zq[k] = pk(lrelu(a0), lrelu(a1));
    }
    float zt[64];
#pragma unroll 8
    for (int k = 0; k < 64; k++) {
        const ulonglong2* wr = (const ulonglong2*)(sw2q + k * 32);
        u64 a0 = 0ull, a1 = 0ull, a2 = 0ull, a3 = 0ull;
#pragma unroll
        for (int j4 = 0; j4 < 8; j4++) {
            ulonglong2 w0 = wr[2 * j4], w1v = wr[2 * j4 + 1];
            a0 = ffma2(w0.x,  zq[4 * j4 + 0], a0);
            a1 = ffma2(w0.y,  zq[4 * j4 + 1], a1);
            a2 = ffma2(w1v.x, zq[4 * j4 + 2], a2);
            a3 = ffma2(w1v.y, zq[4 * j4 + 3], a3);
        }
        float l0, h0, l1, h1, l2, h2, l3, h3;
        unpk(a0, l0, h0); unpk(a1, l1, h1); unpk(a2, l2, h2); unpk(a3, l3, h3);
        zt[k] = lrelu(((l0 + h0) + (l1 + h1)) + ((l2 + h2) + (l3 + h3)) + sb2[k]);
    }
#pragma unroll
    for (int k = 0; k < 32; k++) zq[k] = pk(zt[2 * k], zt[2 * k + 1]);
#pragma unroll 8
    for (int k = 0; k < 64; k++) {
        const ulonglong2* wr = (const ulonglong2*)(sw3q + k * 32);
        u64 a0 = 0ull, a1 = 0ull, a2 = 0ull, a3 = 0ull;
#pragma unroll
        for (int j4 = 0; j4 < 8; j4++) {
            ulonglong2 w0 = wr[2 * j4], w1v = wr[2 * j4 + 1];
            a0 = ffma2(w0.x,  zq[4 * j4 + 0], a0);
            a1 = ffma2(w0.y,  zq[4 * j4 + 1], a1);
            a2 = ffma2(w1v.x, zq[4 * j4 + 2], a2);
            a3 = ffma2(w1v.y, zq[4 * j4 + 3], a3);
        }
        float l0, h0, l1, h1, l2, h2, l3, h3;
        unpk(a0, l0, h0); unpk(a1, l1, h1); unpk(a2, l2, h2); unpk(a3, l3, h3);
        zs[k] = lrelu(((l0 + h0) + (l1 + h1)) + ((l2 + h2) + (l3 + h3)) + sb3[k]);
    }
}

#define SIDX(s) (((s) * 9973) & 65535)

// ---------------- prep: blocks 0..31 sample MLP; block 32 zeros + zero-feat ----------------
__global__ __launch_bounds__(128) void k_prep(
    const float* __restrict__ grid,
    const float* __restrict__ w1, const float* __restrict__ b1,
    const float* __restrict__ w2, const float* __restrict__ b2,
    const float* __restrict__ w3, const float* __restrict__ b3)
{
    int tid = threadIdx.x;
    if (blockIdx.x == NSAMP / 128) {
        __shared__ float z1[64], z2[64];
        if (tid < NCH) g_popcnt[tid] = 0;
        if (tid < NF) g_cnt[tid] = 0;
        if (tid < 64) z1[tid] = lrelu(b1[tid]);
        __syncthreads();
        if (tid < 64) {
            float a = b2[tid];
            for (int j = 0; j < 64; j++) a += w2[tid * 64 + j] * z1[j];
            z2[tid] = lrelu(a);
        }
        __syncthreads();
        if (tid < 64) {
            float a = b3[tid];
            for (int j = 0; j < 64; j++) a += w3[tid * 64 + j] * z2[j];
            g_zf[tid] = lrelu(a);
        }
        return;
    }
    __shared__ float sw1[128], sb1[64], sb2[64], sb3[64];
    __shared__ u64 sw2q[2048], sw3q[2048];
    load_mlp_smem(w1, b1, w2, b2, w3, b3, sw1, sb1, sw2q, sb2, sw3q, sb3, tid, 128);
    __syncthreads();

    int s = blockIdx.x * 128 + tid;
    int n = SIDX(s);
    float zs[64];
    mlp_point(grid[n], grid[NPTS + n], sw1, sb1, sw2q, sb2, sw3q, sb3, zs);
    float4* op = (float4*)(g_sfeat + s * 64);
#pragma unroll
    for (int k = 0; k < 16; k++)
        op[k] = make_float4(zs[4 * k], zs[4 * k + 1], zs[4 * k + 2], zs[4 * k + 3]);
}

// ---------------- select: exact KGUAR-th largest of NSAMP samples per feature ----------------
__global__ __launch_bounds__(32) void k_select() {
    int f = blockIdx.x;
    int lane = threadIdx.x;
    unsigned keys[NSAMP / 32];
#pragma unroll
    for (int i = 0; i < NSAMP / 32; i++)
        keys[i] = okey(g_sfeat[(i * 32 + lane) * 64 + f]);

    unsigned T = 0u;
#pragma unroll
    for (int bit = 31; bit >= 0; bit--) {
        unsigned cand = T | (1u << bit);
        int c = 0;
#pragma unroll
        for (int i = 0; i < NSAMP / 32; i++) c += (keys[i] >= cand);
        c += __shfl_xor_sync(0xffffffffu, c, 16);
        c += __shfl_xor_sync(0xffffffffu, c, 8);
        c += __shfl_xor_sync(0xffffffffu, c, 4);
        c += __shfl_xor_sync(0xffffffffu, c, 2);
        c += __shfl_xor_sync(0xffffffffu, c, 1);
        if (c >= KGUAR) T = cand;
    }
    if (lane == 0) g_T[f] = dekey(T);
}

// ---------------- fused: blocks [0,512) MLP+collect+store; rest pack masks ----------------
__global__ __launch_bounds__(128) void k_main(
    const int* __restrict__ x,
    const float* __restrict__ grid,
    const float* __restrict__ w1, const float* __restrict__ b1,
    const float* __restrict__ w2, const float* __restrict__ b2,
    const float* __restrict__ w3, const float* __restrict__ b3)
{
    __shared__ float sw1[128], sb1[64], sb2[64], sb3[64], sT[64];
    __shared__ u64 sw2q[2048], sw3q[2048];
    __shared__ int sp[4];

    int tid = threadIdx.x;

    if (blockIdx.x >= NCOLBLK) {
        // ---- pack masks ----
        int g = (blockIdx.x - NCOLBLK) * 128 + tid;   // < NCH*NPTS
        int ch = g >> 16;
        int pos = g & 65535;
        int v = (x[g] == 1);
        unsigned ball = __ballot_sync(0xffffffffu, v);
        int lane = tid & 31, wp = tid >> 5;
        if (lane == 0) {
            g_maskT[(pos >> 5) * NCH + ch] = ball;
            sp[wp] = __popc(ball);
        }
        __syncthreads();
        if (tid == 0)
            atomicAdd(&g_popcnt[ch], sp[0] + sp[1] + sp[2] + sp[3]);
        return;
    }

    // ---- collect ----
    load_mlp_smem(w1, b1, w2, b2, w3, b3, sw1, sb1, sw2q, sb2, sw3q, sb3, tid, 128);
    if (tid < 64) sT[tid] = g_T[tid];
    __syncthreads();

    int n = blockIdx.x * 128 + tid;
    float zs[64];
    mlp_point(grid[n], grid[NPTS + n], sw1, sb1, sw2q, sb2, sw3q, sb3, zs);

    float4* op = (float4*)(g_feats + (size_t)n * 64);
#pragma unroll
    for (int k = 0; k < 16; k++)
        op[k] = make_float4(zs[4 * k], zs[4 * k + 1], zs[4 * k + 2], zs[4 * k + 3]);

#pragma unroll
    for (int k = 0; k < 64; k++) {
        if (zs[k] >= sT[k]) {
            int p = atomicAdd(&g_cnt[k], 1);
            g_cand[(size_t)k * CAP + p] = make_int2(n, __float_as_int(zs[k]));
        }
    }
}

// ---------------- per-feature masked max over candidates, 4-slice + batched prefetch ----------------
__global__ __launch_bounds__(512) void k_query() {
    __shared__ float sred[4][128];
    __shared__ unsigned char sfound[4][128];
    __shared__ int s_nfb;
    __shared__ unsigned char sflag[NCH];
    __shared__ float sfb[512];

    int tid = threadIdx.x;
    int ch = tid & 127;           // active < 76
    int sl = tid >> 7;            // candidate slice 0..3
    int f = blockIdx.x;
    int cnt = g_cnt[f];

    if (tid == 0) s_nfb = 0;
    if (tid < NCH) sflag[tid] = 0;

    int per = (cnt + 3) >> 2;
    int i0 = sl * per;
    int i1 = min(cnt, i0 + per);

    float m = -1e30f;
    bool found = false;
    if (ch < NCH) {
        const int2* cd = g_cand + (size_t)f * CAP;
        int i = i0;
        for (; i + 8 <= i1; i += 8) {
            int2 c[8];
#pragma unroll
            for (int u = 0; u < 8; u++) c[u] = __ldg(cd + i + u);
            unsigned w[8];
#pragma unroll
            for (int u = 0; u < 8; u++)
                w[u] = __ldg(&g_maskT[(c[u].x >> 5) * NCH + ch]);
#pragma unroll
            for (int u = 0; u < 8; u++)
                if ((w[u] >> (c[u].x & 31)) & 1) {
                    m = fmaxf(m, __int_as_float(c[u].y));
                    found = true;
                }
        }
        for (; i < i1; i++) {
            int2 c = __ldg(cd + i);
            unsigned w = __ldg(&g_maskT[(c.x >> 5) * NCH + ch]);
            if ((w >> (c.x & 31)) & 1) {
                m = fmaxf(m, __int_as_float(c.y));
                found = true;
            }
        }
    }
    sred[sl][ch] = m;
    sfound[sl][ch] = found;
    __syncthreads();

    if (tid < NCH) {
        float mm = fmaxf(fmaxf(sred[0][tid], sred[1][tid]),
                         fmaxf(sred[2][tid], sred[3][tid]));
        bool ff = sfound[0][tid] | sfound[1][tid] | sfound[2][tid] | sfound[3][tid];
        if (g_popcnt[tid] > 0) {
            if (ff) g_zres[tid * 64 + f] = mm;
            else { sflag[tid] = 1; atomicAdd(&s_nfb, 1); }
        }
    }
    __syncthreads();
    if (s_nfb == 0) return;

    // exact fallback (P ~ 2^-512 per pair): dense scan of stored feature column
    for (int c = 0; c < NCH; c++) {
        if (!sflag[c]) continue;
        float fm = -1e30f;
        for (int base = 0; base < NPTS; base += 512) {
            int n = base + tid;
            float v = __ldg(&g_feats[(size_t)n * 64 + f]);
            unsigned w = g_maskT[(n >> 5) * NCH + c];
            if ((w >> (n & 31)) & 1) fm = fmaxf(fm, v);
        }
        sfb[tid] = fm;
        __syncthreads();
        for (int off = 256; off; off >>= 1) {
            if (tid < off) sfb[tid] = fmaxf(sfb[tid], sfb[tid + off]);
            __syncthreads();
        }
        if (tid == 0) g_zres[c * 64 + f] = sfb[0];
        __syncthreads();
    }
}

// ---------------- final FC + repeat 18 ----------------
__global__ __launch_bounds__(128) void k_fc(const float* __restrict__ fcw,
                                            const float* __restrict__ fcb,
                                            float* __restrict__ out)
{
    __shared__ float fs[NCH * NF];
    __shared__ float rw[4][4];

    int tid = threadIdx.x;
    int o = blockIdx.x;
    for (int i = tid; i < NCH * NF; i += 128) {
        int ch = i >> 6;
        fs[i] = (g_popcnt[ch] > 0) ? g_zres[i] : g_zf[i & 63];
    }
    __syncthreads();

    float p0 = 0.f, p1 = 0.f, p2 = 0.f, p3 = 0.f;
    const float* wr = fcw + o * 1216;
    for (int k = tid; k < 1216; k += 128) {
        float w = wr[k];
        p0 += w * fs[k];
        p1 += w * fs[1216 + k];
        p2 += w * fs[2432 + k];
        p3 += w * fs[3648 + k];
    }
#pragma unroll
    for (int off = 16; off; off >>= 1) {
        p0 += __shfl_xor_sync(0xffffffffu, p0, off);
        p1 += __shfl_xor_sync(0xffffffffu, p1, off);
        p2 += __shfl_xor_sync(0xffffffffu, p2, off);
        p3 += __shfl_xor_sync(0xffffffffu, p3, off);
    }
    int lane = tid & 31, wp = tid >> 5;
    if (lane == 0) { rw[wp][0] = p0; rw[wp][1] = p1; rw[wp][2] = p2; rw[wp][3] = p3; }
    __syncthreads();
    if (tid < 4) {
        float s = rw[0][tid] + rw[1][tid] + rw[2][tid] + rw[3][tid];
        float scale = rsqrtf(1216.0f);
        float val = s * scale + fcb[o];
#pragma unroll
        for (int r = 0; r < 18; r++)
            out[(tid * 18 + r) * 512 + o] = val;
    }
}

extern "C" void kernel_launch(void* const* d_in, const int* in_sizes, int n_in,
                              void* d_out, int out_size) {
    const int*   x    = (const int*)d_in[0];
    const float* grid = (const float*)d_in[1];
    const float* w1   = (const float*)d_in[2];
    const float* b1   = (const float*)d_in[3];
    const float* w2   = (const float*)d_in[4];
    const float* b2   = (const float*)d_in[5];
    const float* w3   = (const float*)d_in[6];
    const float* b3   = (const float*)d_in[7];
    const float* fcw  = (const float*)d_in[8];
    const float* fcb  = (const float*)d_in[9];
    float* out = (float*)d_out;

    k_prep<<<NSAMP / 128 + 1, 128>>>(grid, w1, b1, w2, b2, w3, b3);
    k_select<<<NF, 32>>>();
    k_main<<<NCOLBLK + NPACKBLK, 128>>>(x, grid, w1, b1, w2, b2, w3, b3);
    k_query<<<NF, 512>>>();
    k_fc<<<512, 128>>>(fcw, fcb, out);
}

// round 8
// speedup vs baseline: 1.5397x; 1.0234x over previous
#include <cuda_runtime.h>

#define NPTS 65536
#define NCH 76          // 4*19
#define NF 64
#define CAP 65536       // per-feature candidate cap == NPTS: overflow impossible
#define NSAMP 4096
#define KGUAR 32        // threshold = exact 32nd-largest sample value
#define NWORDTOT (NCH * NPTS / 32)    // 155648 mask words
#define QCHUNK 2048

typedef unsigned long long u64;

__device__ unsigned g_maskT[2048 * NCH];     // [word_in_ch][ch] transposed
__device__ int      g_popcnt[NCH];
__device__ float    g_zres[NCH * NF];
__device__ float    g_zf[NF];                // zero-point fallback feature
__device__ float    g_sfeat[NSAMP * NF];     // sample features [s][f]
__device__ float    g_T[NF];                 // per-feature candidate threshold
__device__ int      g_cnt[NF];
__device__ int2     g_cand[(size_t)NF * CAP];       // (.x = point idx, .y = float bits)
__device__ float    g_feats[(size_t)NPTS * NF];     // [n][f] full features (fallback)

__device__ __forceinline__ float lrelu(float a) { return fmaxf(a, 0.01f * a); }

__device__ __forceinline__ unsigned okey(float f) {
    unsigned u = __float_as_uint(f);
    return u ^ (unsigned)(((int)u >> 31) | (int)0x80000000);
}
__device__ __forceinline__ float dekey(unsigned k) {
    unsigned u = (k & 0x80000000u) ? (k ^ 0x80000000u) : ~k;
    return __uint_as_float(u);
}

// ---- packed f32x2 helpers (sm_100+) ----
__device__ __forceinline__ u64 pk(float lo, float hi) {
    u64 r; asm("mov.b64 %0, {%1,%2};" : "=l"(r) : "f"(lo), "f"(hi)); return r;
}
__device__ __forceinline__ void unpk(u64 a, float& lo, float& hi) {
    asm("mov.b64 {%0,%1}, %2;" : "=f"(lo), "=f"(hi) : "l"(a));
}
__device__ __forceinline__ u64 ffma2(u64 a, u64 b, u64 c) {
    u64 d; asm("fma.rn.f32x2 %0, %1, %2, %3;" : "=l"(d) : "l"(a), "l"(b), "l"(c));
    return d;
}

// ---- shared-memory weight loader ----
__device__ __forceinline__ void load_mlp_smem(
    const float* w1, const float* b1, const float* w2, const float* b2,
    const float* w3, const float* b3,
    float* sw1, float* sb1, u64* sw2q, float* sb2, u64* sw3q, float* sb3,
    int tid, int nt)
{
    for (int i = tid; i < 128; i += nt) sw1[i] = w1[i];
    for (int i = tid; i < 64; i += nt) { sb1[i] = b1[i]; sb2[i] = b2[i]; sb3[i] = b3[i]; }
    for (int i = tid; i < 2048; i += nt) {
        sw2q[i] = ((const u64*)w2)[i];
        sw3q[i] = ((const u64*)w3)[i];
    }
}

// ---- layers 1+2: produce packed layer-2 activations zq[32] ----
__device__ __forceinline__ void mlp_l12(
    float uu, float vv,
    const float* sw1, const float* sb1,
    const u64* sw2q, const float* sb2,
    u64 zq[32])
{
#pragma unroll 8
    for (int k = 0; k < 32; k++) {
        float a0 = fmaf(sw1[4 * k + 0], uu, fmaf(sw1[4 * k + 1], vv, sb1[2 * k]));
        float a1 = fmaf(sw1[4 * k + 2], uu, fmaf(sw1[4 * k + 3], vv, sb1[2 * k + 1]));
        zq[k] = pk(lrelu(a0), lrelu(a1));
    }
    float zt[64];
#pragma unroll 4
    for (int k = 0; k < 64; k++) {
        const ulonglong2* wr = (const ulonglong2*)(sw2q + k * 32);
        u64 a0 = 0ull, a1 = 0ull, a2 = 0ull, a3 = 0ull;
#pragma unroll
        for (int j4 = 0; j4 < 8; j4++) {
            ulonglong2 w0 = wr[2 * j4], w1v = wr[2 * j4 + 1];
            a0 = ffma2(w0.x,  zq[4 * j4 + 0], a0);
            a1 = ffma2(w0.y,  zq[4 * j4 + 1], a1);
            a2 = ffma2(w1v.x, zq[4 * j4 + 2], a2);
            a3 = ffma2(w1v.y, zq[4 * j4 + 3], a3);
        }
        float l0, h0, l1, h1, l2, h2, l3, h3;
        unpk(a0, l0, h0); unpk(a1, l1, h1); unpk(a2, l2, h2); unpk(a3, l3, h3);
        zt[k] = lrelu(((l0 + h0) + (l1 + h1)) + ((l2 + h2) + (l3 + h3)) + sb2[k]);
    }
#pragma unroll
    for (int k = 0; k < 32; k++) zq[k] = pk(zt[2 * k], zt[2 * k + 1]);
}

// one layer-3 output (k given), from packed zq
#define MLP_L3_K(kk, outv) { \
    const ulonglong2* wr3_ = (const ulonglong2*)(sw3q + (kk) * 32); \
    u64 a0_ = 0ull, a1_ = 0ull, a2_ = 0ull, a3_ = 0ull; \
    _Pragma("unroll") \
    for (int j4_ = 0; j4_ < 8; j4_++) { \
        ulonglong2 w0_ = wr3_[2 * j4_], w1_ = wr3_[2 * j4_ + 1]; \
        a0_ = ffma2(w0_.x, zq[4 * j4_ + 0], a0_); \
        a1_ = ffma2(w0_.y, zq[4 * j4_ + 1], a1_); \
        a2_ = ffma2(w1_.x, zq[4 * j4_ + 2], a2_); \
        a3_ = ffma2(w1_.y, zq[4 * j4_ + 3], a3_); \
    } \
    float l0_, h0_, l1_, h1_, l2_, h2_, l3_, h3_; \
    unpk(a0_, l0_, h0_); unpk(a1_, l1_, h1_); unpk(a2_, l2_, h2_); unpk(a3_, l3_, h3_); \
    outv = lrelu(((l0_ + h0_) + (l1_ + h1_)) + ((l2_ + h2_) + (l3_ + h3_)) + sb3[kk]); }

#define SIDX(s) (((s) * 9973) & 65535)

// ---------------- prep: blocks 0..31 sample MLP; block 32 init + zero-feat ----------------
__global__ __launch_bounds__(128) void k_prep(
    const float* __restrict__ grid,
    const float* __restrict__ w1, const float* __restrict__ b1,
    const float* __restrict__ w2, const float* __restrict__ b2,
    const float* __restrict__ w3, const float* __restrict__ b3)
{
    int tid = threadIdx.x;
    if (blockIdx.x == NSAMP / 128) {
        __shared__ float z1[64], z2[64];
        if (tid < NCH) g_popcnt[tid] = 0;
        if (tid < NF) g_cnt[tid] = 0;
        if (tid < 64) z1[tid] = lrelu(b1[tid]);
        __syncthreads();
        if (tid < 64) {
            float a = b2[tid];
            for (int j = 0; j < 64; j++) a += w2[tid * 64 + j] * z1[j];
            z2[tid] = lrelu(a);
        }
        __syncthreads();
        if (tid < 64) {
            float a = b3[tid];
            for (int j = 0; j < 64; j++) a += w3[tid * 64 + j] * z2[j];
            g_zf[tid] = lrelu(a);
        }
        return;
    }
    __shared__ float sw1[128], sb1[64], sb2[64], sb3[64];
    __shared__ u64 sw2q[2048], sw3q[2048];
    load_mlp_smem(w1, b1, w2, b2, w3, b3, sw1, sb1, sw2q, sb2, sw3q, sb3, tid, 128);
    __syncthreads();

    int s = blockIdx.x * 128 + tid;
    int n = SIDX(s);
    u64 zq[32];
    mlp_l12(grid[n], grid[NPTS + n], sw1, sb1, sw2q, sb2, zq);
    float4* op = (float4*)(g_sfeat + s * 64);
#pragma unroll 1
    for (int kg = 0; kg < 16; kg++) {
        float4 v4;
        MLP_L3_K(4 * kg + 0, v4.x);
        MLP_L3_K(4 * kg + 1, v4.y);
        MLP_L3_K(4 * kg + 2, v4.z);
        MLP_L3_K(4 * kg + 3, v4.w);
        op[kg] = v4;
    }
}

// ---------------- select: exact KGUAR-th largest of NSAMP samples per feature ----------------
__global__ __launch_bounds__(32) void k_select() {
    int f = blockIdx.x;
    int lane = threadIdx.x;
    unsigned keys[NSAMP / 32];
#pragma unroll
    for (int i = 0; i < NSAMP / 32; i++)
        keys[i] = okey(g_sfeat[(i * 32 + lane) * 64 + f]);

    unsigned T = 0u;
#pragma unroll
    for (int bit = 31; bit >= 0; bit--) {
        unsigned cand = T | (1u << bit);
        int c = 0;
#pragma unroll
        for (int i = 0; i < NSAMP / 32; i++) c += (keys[i] >= cand);
        c += __shfl_xor_sync(0xffffffffu, c, 16);
        c += __shfl_xor_sync(0xffffffffu, c, 8);
        c += __shfl_xor_sync(0xffffffffu, c, 4);
        c += __shfl_xor_sync(0xffffffffu, c, 2);
        c += __shfl_xor_sync(0xffffffffu, c, 1);
        if (c >= KGUAR) T = cand;
    }
    if (lane == 0) g_T[f] = dekey(T);
}

// ---------------- pack: one thread = one 32-point mask word ----------------
__global__ __launch_bounds__(256) void k_pack(const int* __restrict__ x) {
    __shared__ int sp[8];
    int tid = threadIdx.x;
    int w = blockIdx.x * 256 + tid;              // word id < NWORDTOT
    const int4* xp = (const int4*)x + (size_t)w * 8;
    unsigned word = 0;
#pragma unroll
    for (int i = 0; i < 8; i++) {
        int4 v = __ldg(xp + i);
        word |= (unsigned)(v.x == 1) << (4 * i + 0);
        word |= (unsigned)(v.y == 1) << (4 * i + 1);
        word |= (unsigned)(v.z == 1) << (4 * i + 2);
        word |= (unsigned)(v.w == 1) << (4 * i + 3);
    }
    int ch = w >> 11, wic = w & 2047;            // 2048 words/ch; 8 blocks per channel
    g_maskT[wic * NCH + ch] = word;

    int pc = __popc(word);
#pragma unroll
    for (int off = 16; off; off >>= 1)
        pc += __shfl_xor_sync(0xffffffffu, pc, off);
    if ((tid & 31) == 0) sp[tid >> 5] = pc;
    __syncthreads();
    if (tid == 0) {
        int tot = 0;
#pragma unroll
        for (int i = 0; i < 8; i++) tot += sp[i];
        atomicAdd(&g_popcnt[ch], tot);
    }
}

// ---------------- collect: full MLP, streamed layer-3 + threshold + feats store ----------------
__global__ __launch_bounds__(128) void k_collect(
    const float* __restrict__ grid,
    const float* __restrict__ w1, const float* __restrict__ b1,
    const float* __restrict__ w2, const float* __restrict__ b2,
    const float* __restrict__ w3, const float* __restrict__ b3)
{
    __shared__ float sw1[128], sb1[64], sb2[64], sb3[64], sT[64];
    __shared__ u64 sw2q[2048], sw3q[2048];
    int tid = threadIdx.x;
    load_mlp_smem(w1, b1, w2, b2, w3, b3, sw1, sb1, sw2q, sb2, sw3q, sb3, tid, 128);
    if (tid < 64) sT[tid] = g_T[tid];
    __syncthreads();

    int n = blockIdx.x * 128 + tid;
    u64 zq[32];
    mlp_l12(grid[n], grid[NPTS + n], sw1, sb1, sw2q, sb2, zq);

    float4* op = (float4*)(g_feats + (size_t)n * 64);
#pragma unroll 1
    for (int kg = 0; kg < 16; kg++) {
        float4 v4;
        MLP_L3_K(4 * kg + 0, v4.x);
        MLP_L3_K(4 * kg + 1, v4.y);
        MLP_L3_K(4 * kg + 2, v4.z);
        MLP_L3_K(4 * kg + 3, v4.w);
        op[kg] = v4;
#pragma unroll
        for (int q = 0; q < 4; q++) {
            int k = 4 * kg + q;
            float v = (q == 0) ? v4.x : (q == 1) ? v4.y : (q == 2) ? v4.z : v4.w;
            if (v >= sT[k]) {
                int p = atomicAdd(&g_cnt[k], 1);
                g_cand[(size_t)k * CAP + p] = make_int2(n, __float_as_int(v));
            }
        }
    }
}

// ---------------- query: smem-staged candidates, 8 slices x 128 ch ----------------
__global__ __launch_bounds__(1024) void k_query() {
    __shared__ int2 scand[QCHUNK];               // 16KB
    __shared__ float sred[8][128];
    __shared__ unsigned char sfnd[8][128];
    __shared__ int s_nfb;
    __shared__ unsigned char sflag[NCH];
    __shared__ float sfb[1024];

    int tid = threadIdx.x;
    int ch = tid & 127;           // active < 76
    int sl = tid >> 7;            // 8 slices
    int f = blockIdx.x;
    int cnt = g_cnt[f];

    if (tid == 0) s_nfb = 0;
    if (tid < NCH) sflag[tid] = 0;

    float m = -1e30f;
    bool found = false;
    for (int base = 0; base < cnt; base += QCHUNK) {
        int len = min(QCHUNK, cnt - base);
        __syncthreads();
        for (int i = tid; i < len; i += 1024)
            scand[i] = __ldg(g_cand + (size_t)f * CAP + base + i);
        __syncthreads();
        if (ch < NCH) {
            int per = (len + 7) >> 3;
            int i0 = sl * per, i1 = min(len, i0 + per);
            int i = i0;
            for (; i + 4 <= i1; i += 4) {
                int2 c0 = scand[i], c1 = scand[i + 1], c2 = scand[i + 2], c3 = scand[i + 3];
                unsigned w0 = __ldg(&g_maskT[(c0.x >> 5) * NCH + ch]);
                unsigned w1 = __ldg(&g_maskT[(c1.x >> 5) * NCH + ch]);
                unsigned w2 = __ldg(&g_maskT[(c2.x >> 5) * NCH + ch]);
                unsigned w3 = __ldg(&g_maskT[(c3.x >> 5) * NCH + ch]);
                if ((w0 >> (c0.x & 31)) & 1) { m = fmaxf(m, __int_as_float(c0.y)); found = true; }
                if ((w1 >> (c1.x & 31)) & 1) { m = fmaxf(m, __int_as_float(c1.y)); found = true; }
                if ((w2 >> (c2.x & 31)) & 1) { m = fmaxf(m, __int_as_float(c2.y)); found = true; }
                if ((w3 >> (c3.x & 31)) & 1) { m = fmaxf(m, __int_as_float(c3.y)); found = true; }
            }
            for (; i < i1; i++) {
                int2 c = scand[i];
                unsigned w = __ldg(&g_maskT[(c.x >> 5) * NCH + ch]);
                if ((w >> (c.x & 31)) & 1) { m = fmaxf(m, __int_as_float(c.y)); found = true; }
            }
        }
    }
    sred[sl][ch] = m;
    sfnd[sl][ch] = found;
    __syncthreads();

    if (tid < NCH) {
        float mm = -1e30f;
        int ff = 0;
#pragma unroll
        for (int s = 0; s < 8; s++) { mm = fmaxf(mm, sred[s][tid]); ff |= sfnd[s][tid]; }
        if (g_popcnt[tid] > 0) {
            if (ff) g_zres[tid * 64 + f] = mm;
            else { sflag[tid] = 1; atomicAdd(&s_nfb, 1); }
        }
    }
    __syncthreads();
    if (s_nfb == 0) return;

    // exact fallback (P ~ 2^-512 per pair): dense scan of stored feature column
    for (int c = 0; c < NCH; c++) {
        if (!sflag[c]) continue;
        float fm = -1e30f;
        for (int base = 0; base < NPTS; base += 1024) {
            int n = base + tid;
            float v = __ldg(&g_feats[(size_t)n * 64 + f]);
            unsigned w = g_maskT[(n >> 5) * NCH + c];
            if ((w >> (n & 31)) & 1) fm = fmaxf(fm, v);
        }
        sfb[tid] = fm;
        __syncthreads();
        for (int off = 512; off; off >>= 1) {
            if (tid < off) sfb[tid] = fmaxf(sfb[tid], sfb[tid + off]);
            __syncthreads();
        }
        if (tid == 0) g_zres[c * 64 + f] = sfb[0];
        __syncthreads();
    }
}

// ---------------- final FC + repeat 18 ----------------
__global__ __launch_bounds__(128) void k_fc(const float* __restrict__ fcw,
                                            const float* __restrict__ fcb,
                                            float* __restrict__ out)
{
    __shared__ float fs[NCH * NF];
    __shared__ float rw[4][4];

    int tid = threadIdx.x;
    int o = blockIdx.x;
    for (int i = tid; i < NCH * NF; i += 128) {
        int ch = i >> 6;
        fs[i] = (g_popcnt[ch] > 0) ? g_zres[i] : g_zf[i & 63];
    }
    __syncthreads();

    float p0 = 0.f, p1 = 0.f, p2 = 0.f, p3 = 0.f;
    const float* wr = fcw + o * 1216;
    for (int k = tid; k < 1216; k += 128) {
        float w = wr[k];
        p0 += w * fs[k];
        p1 += w * fs[1216 + k];
        p2 += w * fs[2432 + k];
        p3 += w * fs[3648 + k];
    }
#pragma unroll
    for (int off = 16; off; off >>= 1) {
        p0 += __shfl_xor_sync(0xffffffffu, p0, off);
        p1 += __shfl_xor_sync(0xffffffffu, p1, off);
        p2 += __shfl_xor_sync(0xffffffffu, p2, off);
        p3 += __shfl_xor_sync(0xffffffffu, p3, off);
    }
    int lane = tid & 31, wp = tid >> 5;
    if (lane == 0) { rw[wp][0] = p0; rw[wp][1] = p1; rw[wp][2] = p2; rw[wp][3] = p3; }
    __syncthreads();
    if (tid < 4) {
        float s = rw[0][tid] + rw[1][tid] + rw[2][tid] + rw[3][tid];
        float scale = rsqrtf(1216.0f);
        float val = s * scale + fcb[o];
#pragma unroll
        for (int r = 0; r < 18; r++)
            out[(tid * 18 + r) * 512 + o] = val;
    }
}

extern "C" void kernel_launch(void* const* d_in, const int* in_sizes, int n_in,
                              void* d_out, int out_size) {
    const int*   x    = (const int*)d_in[0];
    const float* grid = (const float*)d_in[1];
    const float* w1   = (const float*)d_in[2];
    const float* b1   = (const float*)d_in[3];
    const float* w2   = (const float*)d_in[4];
    const float* b2   = (const float*)d_in[5];
    const float* w3   = (const float*)d_in[6];
    const float* b3   = (const float*)d_in[7];
    const float* fcw  = (const float*)d_in[8];
    const float* fcb  = (const float*)d_in[9];
    float* out = (float*)d_out;

    k_prep<<<NSAMP / 128 + 1, 128>>>(grid, w1, b1, w2, b2, w3, b3);
    k_select<<<NF, 32>>>();
    k_pack<<<NWORDTOT / 256, 256>>>(x);
    k_collect<<<NPTS / 128, 128>>>(grid, w1, b1, w2, b2, w3, b3);
    k_query<<<NF, 1024>>>();
    k_fc<<<512, 128>>>(fcw, fcb, out);
}

// round 9
// speedup vs baseline: 1.5470x; 1.0047x over previous
#include <cuda_runtime.h>

#define NPTS 65536
#define NCH 76          // 4*19
#define NF 64
#define CAP 65536       // per-feature candidate cap == NPTS: overflow impossible
#define NSAMP 4096
#define KGUAR 32        // threshold = exact 32nd-largest sample value
#define NWORDTOT (NCH * NPTS / 32)    // 155648 mask words
#define QCHUNK 2048

typedef unsigned long long u64;

__device__ unsigned g_maskT[2048 * NCH];     // [word_in_ch][ch] transposed
__device__ int      g_popcnt[NCH];
__device__ float    g_zres[NCH * NF];
__device__ float    g_zf[NF];                // zero-point fallback feature
__device__ float    g_sfeat[NSAMP * NF];     // sample features [s][f]
__device__ float    g_T[NF];                 // per-feature candidate threshold
__device__ int      g_cnt[NF];
__device__ int2     g_cand[(size_t)NF * CAP];       // (.x = point idx, .y = float bits)
__device__ float    g_feats[(size_t)NPTS * NF];     // [n][f] full features (fallback)

__device__ __forceinline__ float lrelu(float a) { return fmaxf(a, 0.01f * a); }

__device__ __forceinline__ unsigned okey(float f) {
    unsigned u = __float_as_uint(f);
    return u ^ (unsigned)(((int)u >> 31) | (int)0x80000000);
}
__device__ __forceinline__ float dekey(unsigned k) {
    unsigned u = (k & 0x80000000u) ? (k ^ 0x80000000u) : ~k;
    return __uint_as_float(u);
}

// ---- packed f32x2 helpers (sm_100+) ----
__device__ __forceinline__ u64 pk(float lo, float hi) {
    u64 r; asm("mov.b64 %0, {%1,%2};" : "=l"(r) : "f"(lo), "f"(hi)); return r;
}
__device__ __forceinline__ void unpk(u64 a, float& lo, float& hi) {
    asm("mov.b64 {%0,%1}, %2;" : "=f"(lo), "=f"(hi) : "l"(a));
}
__device__ __forceinline__ u64 ffma2(u64 a, u64 b, u64 c) {
    u64 d; asm("fma.rn.f32x2 %0, %1, %2, %3;" : "=l"(d) : "l"(a), "l"(b), "l"(c));
    return d;
}

// ---- shared-memory weight loader ----
__device__ __forceinline__ void load_mlp_smem(
    const float* w1, const float* b1, const float* w2, const float* b2,
    const float* w3, const float* b3,
    float* sw1, float* sb1, u64* sw2q, float* sb2, u64* sw3q, float* sb3,
    int tid, int nt)
{
    for (int i = tid; i < 128; i += nt) sw1[i] = w1[i];
    for (int i = tid; i < 64; i += nt) { sb1[i] = b1[i]; sb2[i] = b2[i]; sb3[i] = b3[i]; }
    for (int i = tid; i < 2048; i += nt) {
        sw2q[i] = ((const u64*)w2)[i];
        sw3q[i] = ((const u64*)w3)[i];
    }
}

// ---- layers 1+2: produce packed layer-2 activations zq[32] ----
__device__ __forceinline__ void mlp_l12(
    float uu, float vv,
    const float* sw1, const float* sb1,
    const u64* sw2q, const float* sb2,
    u64 zq[32])
{
#pragma unroll 8
    for (int k = 0; k < 32; k++) {
        float a0 = fmaf(sw1[4 * k + 0], uu, fmaf(sw1[4 * k + 1], vv, sb1[2 * k]));
        float a1 = fmaf(sw1[4 * k + 2], uu, fmaf(sw1[4 * k + 3], vv, sb1[2 * k + 1]));
        zq[k] = pk(lrelu(a0), lrelu(a1));
    }
    float zt[64];
#pragma unroll 4
    for (int k = 0; k < 64; k++) {
        const ulonglong2* wr = (const ulonglong2*)(sw2q + k * 32);
        u64 a0 = 0ull, a1 = 0ull, a2 = 0ull, a3 = 0ull;
#pragma unroll
        for (int j4 = 0; j4 < 8; j4++) {
            ulonglong2 w0 = wr[2 * j4], w1v = wr[2 * j4 + 1];
            a0 = ffma2(w0.x,  zq[4 * j4 + 0], a0);
            a1 = ffma2(w0.y,  zq[4 * j4 + 1], a1);
            a2 = ffma2(w1v.x, zq[4 * j4 + 2], a2);
            a3 = ffma2(w1v.y, zq[4 * j4 + 3], a3);
        }
        float l0, h0, l1, h1, l2, h2, l3, h3;
        unpk(a0, l0, h0); unpk(a1, l1, h1); unpk(a2, l2, h2); unpk(a3, l3, h3);
        zt[k] = lrelu(((l0 + h0) + (l1 + h1)) + ((l2 + h2) + (l3 + h3)) + sb2[k]);
    }
#pragma unroll
    for (int k = 0; k < 32; k++) zq[k] = pk(zt[2 * k], zt[2 * k + 1]);
}

// one layer-3 output (k given), from packed zq
#define MLP_L3_K(kk, outv) { \
    const ulonglong2* wr3_ = (const ulonglong2*)(sw3q + (kk) * 32); \
    u64 a0_ = 0ull, a1_ = 0ull, a2_ = 0ull, a3_ = 0ull; \
    _Pragma("unroll") \
    for (int j4_ = 0; j4_ < 8; j4_++) { \
        ulonglong2 w0_ = wr3_[2 * j4_], w1_ = wr3_[2 * j4_ + 1]; \
        a0_ = ffma2(w0_.x, zq[4 * j4_ + 0], a0_); \
        a1_ = ffma2(w0_.y, zq[4 * j4_ + 1], a1_); \
        a2_ = ffma2(w1_.x, zq[4 * j4_ + 2], a2_); \
        a3_ = ffma2(w1_.y, zq[4 * j4_ + 3], a3_); \
    } \
    float l0_, h0_, l1_, h1_, l2_, h2_, l3_, h3_; \
    unpk(a0_, l0_, h0_); unpk(a1_, l1_, h1_); unpk(a2_, l2_, h2_); unpk(a3_, l3_, h3_); \
    outv = lrelu(((l0_ + h0_) + (l1_ + h1_)) + ((l2_ + h2_) + (l3_ + h3_)) + sb3[kk]); }

#define SIDX(s) (((s) * 9973) & 65535)

// ---------------- prep: blocks 0..31 sample MLP; block 32 init + zero-feat ----------------
__global__ __launch_bounds__(128) void k_prep(
    const float* __restrict__ grid,
    const float* __restrict__ w1, const float* __restrict__ b1,
    const float* __restrict__ w2, const float* __restrict__ b2,
    const float* __restrict__ w3, const float* __restrict__ b3)
{
    int tid = threadIdx.x;
    if (blockIdx.x == NSAMP / 128) {
        __shared__ float z1[64], z2[64];
        if (tid < NCH) g_popcnt[tid] = 0;
        if (tid < NF) g_cnt[tid] = 0;
        if (tid < 64) z1[tid] = lrelu(b1[tid]);
        __syncthreads();
        if (tid < 64) {
            float a = b2[tid];
            for (int j = 0; j < 64; j++) a += w2[tid * 64 + j] * z1[j];
            z2[tid] = lrelu(a);
        }
        __syncthreads();
        if (tid < 64) {
            float a = b3[tid];
            for (int j = 0; j < 64; j++) a += w3[tid * 64 + j] * z2[j];
            g_zf[tid] = lrelu(a);
        }
        return;
    }
    __shared__ float sw1[128], sb1[64], sb2[64], sb3[64];
    __shared__ u64 sw2q[2048], sw3q[2048];
    load_mlp_smem(w1, b1, w2, b2, w3, b3, sw1, sb1, sw2q, sb2, sw3q, sb3, tid, 128);
    __syncthreads();

    int s = blockIdx.x * 128 + tid;
    int n = SIDX(s);
    u64 zq[32];
    mlp_l12(grid[n], grid[NPTS + n], sw1, sb1, sw2q, sb2, zq);
    float4* op = (float4*)(g_sfeat + s * 64);
#pragma unroll 1
    for (int kg = 0; kg < 16; kg++) {
        float4 v4;
        MLP_L3_K(4 * kg + 0, v4.x);
        MLP_L3_K(4 * kg + 1, v4.y);
        MLP_L3_K(4 * kg + 2, v4.z);
        MLP_L3_K(4 * kg + 3, v4.w);
        op[kg] = v4;
    }
}

// ---------------- select: exact KGUAR-th largest of NSAMP samples per feature ----------------
__global__ __launch_bounds__(32) void k_select() {
    int f = blockIdx.x;
    int lane = threadIdx.x;
    unsigned keys[NSAMP / 32];
#pragma unroll
    for (int i = 0; i < NSAMP / 32; i++)
        keys[i] = okey(g_sfeat[(i * 32 + lane) * 64 + f]);

    unsigned T = 0u;
#pragma unroll
    for (int bit = 31; bit >= 0; bit--) {
        unsigned cand = T | (1u << bit);
        int c = 0;
#pragma unroll
        for (int i = 0; i < NSAMP / 32; i++) c += (keys[i] >= cand);
        c += __shfl_xor_sync(0xffffffffu, c, 16);
        c += __shfl_xor_sync(0xffffffffu, c, 8);
        c += __shfl_xor_sync(0xffffffffu, c, 4);
        c += __shfl_xor_sync(0xffffffffu, c, 2);
        c += __shfl_xor_sync(0xffffffffu, c, 1);
        if (c >= KGUAR) T = cand;
    }
    if (lane == 0) g_T[f] = dekey(T);
}

// ---------------- pack: one thread = one 32-point mask word ----------------
__global__ __launch_bounds__(256) void k_pack(const int* __restrict__ x) {
    __shared__ int sp[8];
    int tid = threadIdx.x;
    int w = blockIdx.x * 256 + tid;              // word id < NWORDTOT
    const int4* xp = (const int4*)x + (size_t)w * 8;
    unsigned word = 0;
#pragma unroll
    for (int i = 0; i < 8; i++) {
        int4 v = __ldg(xp + i);
        word |= (unsigned)(v.x == 1) << (4 * i + 0);
        word |= (unsigned)(v.y == 1) << (4 * i + 1);
        word |= (unsigned)(v.z == 1) << (4 * i + 2);
        word |= (unsigned)(v.w == 1) << (4 * i + 3);
    }
    int ch = w >> 11, wic = w & 2047;            // 2048 words/ch; 8 blocks per channel
    g_maskT[wic * NCH + ch] = word;

    int pc = __popc(word);
#pragma unroll
    for (int off = 16; off; off >>= 1)
        pc += __shfl_xor_sync(0xffffffffu, pc, off);
    if ((tid & 31) == 0) sp[tid >> 5] = pc;
    __syncthreads();
    if (tid == 0) {
        int tot = 0;
#pragma unroll
        for (int i = 0; i < 8; i++) tot += sp[i];
        atomicAdd(&g_popcnt[ch], tot);
    }
}

// ---------------- collect: full MLP, streamed layer-3 + threshold + feats store ----------------
__global__ __launch_bounds__(128) void k_collect(
    const float* __restrict__ grid,
    const float* __restrict__ w1, const float* __restrict__ b1,
    const float* __restrict__ w2, const float* __restrict__ b2,
    const float* __restrict__ w3, const float* __restrict__ b3)
{
    __shared__ float sw1[128], sb1[64], sb2[64], sb3[64], sT[64];
    __shared__ u64 sw2q[2048], sw3q[2048];
    int tid = threadIdx.x;
    load_mlp_smem(w1, b1, w2, b2, w3, b3, sw1, sb1, sw2q, sb2, sw3q, sb3, tid, 128);
    if (tid < 64) sT[tid] = g_T[tid];
    __syncthreads();

    int n = blockIdx.x * 128 + tid;
    u64 zq[32];
    mlp_l12(grid[n], grid[NPTS + n], sw1, sb1, sw2q, sb2, zq);

    float4* op = (float4*)(g_feats + (size_t)n * 64);
#pragma unroll 1
    for (int kg = 0; kg < 16; kg++) {
        float4 v4;
        MLP_L3_K(4 * kg + 0, v4.x);
        MLP_L3_K(4 * kg + 1, v4.y);
        MLP_L3_K(4 * kg + 2, v4.z);
        MLP_L3_K(4 * kg + 3, v4.w);
        op[kg] = v4;
#pragma unroll
        for (int q = 0; q < 4; q++) {
            int k = 4 * kg + q;
            float v = (q == 0) ? v4.x : (q == 1) ? v4.y : (q == 2) ? v4.z : v4.w;
            if (v >= sT[k]) {
                int p = atomicAdd(&g_cnt[k], 1);
                g_cand[(size_t)k * CAP + p] = make_int2(n, __float_as_int(v));
            }
        }
    }
}

// ---------------- query: smem-staged candidates, 8 slices x 128 ch ----------------
__global__ __launch_bounds__(1024) void k_query() {
    __shared__ int2 scand[QCHUNK];               // 16KB
    __shared__ float sred[8][128];
    __shared__ unsigned char sfnd[8][128];
    __shared__ int s_nfb;
    __shared__ unsigned char sflag[NCH];
    __shared__ float sfb[1024];

    int tid = threadIdx.x;
    int ch = tid & 127;           // active < 76
    int sl = tid >> 7;            // 8 slices
    int f = blockIdx.x;
    int cnt = g_cnt[f];

    if (tid == 0) s_nfb = 0;
    if (tid < NCH) sflag[tid] = 0;

    float m = -1e30f;
    bool found = false;
    for (int base = 0; base < cnt; base += QCHUNK) {
        int len = min(QCHUNK, cnt - base);
        __syncthreads();
        for (int i = tid; i < len; i += 1024)
            scand[i] = __ldg(g_cand + (size_t)f * CAP + base + i);
        __syncthreads();
        if (ch < NCH) {
            int per = (len + 7) >> 3;
            int i0 = sl * per, i1 = min(len, i0 + per);
            int i = i0;
            for (; i + 4 <= i1; i += 4) {
                int2 c0 = scand[i], c1 = scand[i + 1], c2 = scand[i + 2], c3 = scand[i + 3];
                unsigned w0 = __ldg(&g_maskT[(c0.x >> 5) * NCH + ch]);
                unsigned w1 = __ldg(&g_maskT[(c1.x >> 5) * NCH + ch]);
                unsigned w2 = __ldg(&g_maskT[(c2.x >> 5) * NCH + ch]);
                unsigned w3 = __ldg(&g_maskT[(c3.x >> 5) * NCH + ch]);
                if ((w0 >> (c0.x & 31)) & 1) { m = fmaxf(m, __int_as_float(c0.y)); found = true; }
                if ((w1 >> (c1.x & 31)) & 1) { m = fmaxf(m, __int_as_float(c1.y)); found = true; }
                if ((w2 >> (c2.x & 31)) & 1) { m = fmaxf(m, __int_as_float(c2.y)); found = true; }
                if ((w3 >> (c3.x & 31)) & 1) { m = fmaxf(m, __int_as_float(c3.y)); found = true; }
            }
            for (; i < i1; i++) {
                int2 c = scand[i];
                unsigned w = __ldg(&g_maskT[(c.x >> 5) * NCH + ch]);
                if ((w >> (c.x & 31)) & 1) { m = fmaxf(m, __int_as_float(c.y)); found = true; }
            }
        }
    }
    sred[sl][ch] = m;
    sfnd[sl][ch] = found;
    __syncthreads();

    if (tid < NCH) {
        float mm = -1e30f;
        int ff = 0;
#pragma unroll
        for (int s = 0; s < 8; s++) { mm = fmaxf(mm, sred[s][tid]); ff |= sfnd[s][tid]; }
        if (g_popcnt[tid] > 0) {
            if (ff) g_zres[tid * 64 + f] = mm;
            else { sflag[tid] = 1; atomicAdd(&s_nfb, 1); }
        }
    }
    __syncthreads();
    if (s_nfb == 0) return;

    // exact fallback (P ~ 2^-512 per pair): dense scan of stored feature column
    for (int c = 0; c < NCH; c++) {
        if (!sflag[c]) continue;
        float fm = -1e30f;
        for (int base = 0; base < NPTS; base += 1024) {
            int n = base + tid;
            float v = __ldg(&g_feats[(size_t)n * 64 + f]);
            unsigned w = g_maskT[(n >> 5) * NCH + c];
            if ((w >> (n & 31)) & 1) fm = fmaxf(fm, v);
        }
        sfb[tid] = fm;
        __syncthreads();
        for (int off = 512; off; off >>= 1) {
            if (tid < off) sfb[tid] = fmaxf(sfb[tid], sfb[tid + off]);
            __syncthreads();
        }
        if (tid == 0) g_zres[c * 64 + f] = sfb[0];
        __syncthreads();
    }
}

// ---------------- final FC + repeat 18 ----------------
__global__ __launch_bounds__(128) void k_fc(const float* __restrict__ fcw,
                                            const float* __restrict__ fcb,
                                            float* __restrict__ out)
{
    __shared__ float fs[NCH * NF];
    __shared__ float rw[4][4];

    int tid = threadIdx.x;
    int o = blockIdx.x;
    for (int i = tid; i < NCH * NF; i += 128) {
        int ch = i >> 6;
        fs[i] = (g_popcnt[ch] > 0) ? g_zres[i] : g_zf[i & 63];
    }
    __syncthreads();

    float p0 = 0.f, p1 = 0.f, p2 = 0.f, p3 = 0.f;
    const float* wr = fcw + o * 1216;
    for (int k = tid; k < 1216; k += 128) {
        float w = wr[k];
        p0 += w * fs[k];
        p1 += w * fs[1216 + k];
        p2 += w * fs[2432 + k];
        p3 += w * fs[3648 + k];
    }
#pragma unroll
    for (int off = 16; off; off >>= 1) {
        p0 += __shfl_xor_sync(0xffffffffu, p0, off);
        p1 += __shfl_xor_sync(0xffffffffu, p1, off);
        p2 += __shfl_xor_sync(0xffffffffu, p2, off);
        p3 += __shfl_xor_sync(0xffffffffu, p3, off);
    }
    int lane = tid & 31, wp = tid >> 5;
    if (lane == 0) { rw[wp][0] = p0; rw[wp][1] = p1; rw[wp][2] = p2; rw[wp][3] = p3; }
    __syncthreads();
    if (tid < 4) {
        float s = rw[0][tid] + rw[1][tid] + rw[2][tid] + rw[3][tid];
        float scale = rsqrtf(1216.0f);
        float val = s * scale + fcb[o];
#pragma unroll
        for (int r = 0; r < 18; r++)
            out[(tid * 18 + r) * 512 + o] = val;
    }
}

extern "C" void kernel_launch(void* const* d_in, const int* in_sizes, int n_in,
                              void* d_out, int out_size) {
    const int*   x    = (const int*)d_in[0];
    const float* grid = (const float*)d_in[1];
    const float* w1   = (const float*)d_in[2];
    const float* b1   = (const float*)d_in[3];
    const float* w2   = (const float*)d_in[4];
    const float* b2   = (const float*)d_in[5];
    const float* w3   = (const float*)d_in[6];
    const float* b3   = (const float*)d_in[7];
    const float* fcw  = (const float*)d_in[8];
    const float* fcb  = (const float*)d_in[9];
    float* out = (float*)d_out;

    k_prep<<<NSAMP / 128 + 1, 128>>>(grid, w1, b1, w2, b2, w3, b3);
    k_select<<<NF, 32>>>();
    k_pack<<<NWORDTOT / 256, 256>>>(x);
    k_collect<<<NPTS / 128, 128>>>(grid, w1, b1, w2, b2, w3, b3);
    k_query<<<NF, 1024>>>();
    k_fc<<<512, 128>>>(fcw, fcb, out);
}

// round 10
// speedup vs baseline: 1.5621x; 1.0098x over previous
#include <cuda_runtime.h>

#define NPTS 65536
#define NCH 76          // 4*19
#define NF 64
#define CAP 65536       // per-feature candidate cap == NPTS: overflow impossible
#define NSAMP 4096
#define KGUAR 32        // threshold = exact 32nd-largest sample value
#define NWORDTOT (NCH * NPTS / 32)    // 155648 mask words
#define QCHUNK 2048

typedef unsigned long long u64;

__device__ unsigned g_maskT[2048 * NCH];     // [word_in_ch][ch] transposed
__device__ int      g_popcnt[NCH];
__device__ float    g_zres[NCH * NF];
__device__ float    g_zf[NF];                // zero-point fallback feature
__device__ float    g_sfeat[NSAMP * NF];     // sample features [s][f]
__device__ float    g_T[NF];                 // per-feature candidate threshold
__device__ int      g_cnt[NF];
__device__ int2     g_cand[(size_t)NF * CAP];       // (.x = point idx, .y = float bits)
__device__ float    g_feats[(size_t)NPTS * NF];     // [n][f] full features (fallback)

__device__ __forceinline__ float lrelu(float a) { return fmaxf(a, 0.01f * a); }

__device__ __forceinline__ unsigned okey(float f) {
    unsigned u = __float_as_uint(f);
    return u ^ (unsigned)(((int)u >> 31) | (int)0x80000000);
}
__device__ __forceinline__ float dekey(unsigned k) {
    unsigned u = (k & 0x80000000u) ? (k ^ 0x80000000u) : ~k;
    return __uint_as_float(u);
}

// ---- packed f32x2 helpers (sm_100+) ----
__device__ __forceinline__ u64 pk(float lo, float hi) {
    u64 r; asm("mov.b64 %0, {%1,%2};" : "=l"(r) : "f"(lo), "f"(hi)); return r;
}
__device__ __forceinline__ void unpk(u64 a, float& lo, float& hi) {
    asm("mov.b64 {%0,%1}, %2;" : "=f"(lo), "=f"(hi) : "l"(a));
}
__device__ __forceinline__ u64 ffma2(u64 a, u64 b, u64 c) {
    u64 d; asm("fma.rn.f32x2 %0, %1, %2, %3;" : "=l"(d) : "l"(a), "l"(b), "l"(c));
    return d;
}

// ---- shared-memory weight loader ----
__device__ __forceinline__ void load_mlp_smem(
    const float* w1, const float* b1, const float* w2, const float* b2,
    const float* w3, const float* b3,
    float* sw1, float* sb1, u64* sw2q, float* sb2, u64* sw3q, float* sb3,
    int tid, int nt)
{
    for (int i = tid; i < 128; i += nt) sw1[i] = w1[i];
    for (int i = tid; i < 64; i += nt) { sb1[i] = b1[i]; sb2[i] = b2[i]; sb3[i] = b3[i]; }
    for (int i = tid; i < 2048; i += nt) {
        sw2q[i] = ((const u64*)w2)[i];
        sw3q[i] = ((const u64*)w3)[i];
    }
}

// ---- layers 1+2: produce packed layer-2 activations zq[32] ----
__device__ __forceinline__ void mlp_l12(
    float uu, float vv,
    const float* sw1, const float* sb1,
    const u64* sw2q, const float* sb2,
    u64 zq[32])
{
#pragma unroll 8
    for (int k = 0; k < 32; k++) {
        float a0 = fmaf(sw1[4 * k + 0], uu, fmaf(sw1[4 * k + 1], vv, sb1[2 * k]));
        float a1 = fmaf(sw1[4 * k + 2], uu, fmaf(sw1[4 * k + 3], vv, sb1[2 * k + 1]));
        zq[k] = pk(lrelu(a0), lrelu(a1));
    }
    float zt[64];
#pragma unroll 4
    for (int k = 0; k < 64; k++) {
        const ulonglong2* wr = (const ulonglong2*)(sw2q + k * 32);
        u64 a0 = 0ull, a1 = 0ull, a2 = 0ull, a3 = 0ull;
#pragma unroll
        for (int j4 = 0; j4 < 8; j4++) {
            ulonglong2 w0 = wr[2 * j4], w1v = wr[2 * j4 + 1];
            a0 = ffma2(w0.x,  zq[4 * j4 + 0], a0);
            a1 = ffma2(w0.y,  zq[4 * j4 + 1], a1);
            a2 = ffma2(w1v.x, zq[4 * j4 + 2], a2);
            a3 = ffma2(w1v.y, zq[4 * j4 + 3], a3);
        }
        float l0, h0, l1, h1, l2, h2, l3, h3;
        unpk(a0, l0, h0); unpk(a1, l1, h1); unpk(a2, l2, h2); unpk(a3, l3, h3);
        zt[k] = lrelu(((l0 + h0) + (l1 + h1)) + ((l2 + h2) + (l3 + h3)) + sb2[k]);
    }
#pragma unroll
    for (int k = 0; k < 32; k++) zq[k] = pk(zt[2 * k], zt[2 * k + 1]);
}

// one layer-3 output (k given), from packed zq
#define MLP_L3_K(kk, outv) { \
    const ulonglong2* wr3_ = (const ulonglong2*)(sw3q + (kk) * 32); \
    u64 a0_ = 0ull, a1_ = 0ull, a2_ = 0ull, a3_ = 0ull; \
    _Pragma("unroll") \
    for (int j4_ = 0; j4_ < 8; j4_++) { \
        ulonglong2 w0_ = wr3_[2 * j4_], w1_ = wr3_[2 * j4_ + 1]; \
        a0_ = ffma2(w0_.x, zq[4 * j4_ + 0], a0_); \
        a1_ = ffma2(w0_.y, zq[4 * j4_ + 1], a1_); \
        a2_ = ffma2(w1_.x, zq[4 * j4_ + 2], a2_); \
        a3_ = ffma2(w1_.y, zq[4 * j4_ + 3], a3_); \
    } \
    float l0_, h0_, l1_, h1_, l2_, h2_, l3_, h3_; \
    unpk(a0_, l0_, h0_); unpk(a1_, l1_, h1_); unpk(a2_, l2_, h2_); unpk(a3_, l3_, h3_); \
    outv = lrelu(((l0_ + h0_) + (l1_ + h1_)) + ((l2_ + h2_) + (l3_ + h3_)) + sb3[kk]); }

#define SIDX(s) (((s) * 9973) & 65535)

// ---------------- prep: blocks 0..31 sample MLP; block 32 init + zero-feat ----------------
__global__ __launch_bounds__(128) void k_prep(
    const float* __restrict__ grid,
    const float* __restrict__ w1, const float* __restrict__ b1,
    const float* __restrict__ w2, const float* __restrict__ b2,
    const float* __restrict__ w3, const float* __restrict__ b3)
{
    int tid = threadIdx.x;
    if (blockIdx.x == NSAMP / 128) {
        __shared__ float z1[64], z2[64];
        if (tid < NCH) g_popcnt[tid] = 0;
        if (tid < NF) g_cnt[tid] = 0;
        if (tid < 64) z1[tid] = lrelu(b1[tid]);
        __syncthreads();
        if (tid < 64) {
            float a = b2[tid];
            for (int j = 0; j < 64; j++) a += w2[tid * 64 + j] * z1[j];
            z2[tid] = lrelu(a);
        }
        __syncthreads();
        if (tid < 64) {
            float a = b3[tid];
            for (int j = 0; j < 64; j++) a += w3[tid * 64 + j] * z2[j];
            g_zf[tid] = lrelu(a);
        }
        return;
    }
    __shared__ float sw1[128], sb1[64], sb2[64], sb3[64];
    __shared__ u64 sw2q[2048], sw3q[2048];
    load_mlp_smem(w1, b1, w2, b2, w3, b3, sw1, sb1, sw2q, sb2, sw3q, sb3, tid, 128);
    __syncthreads();

    int s = blockIdx.x * 128 + tid;
    int n = SIDX(s);
    u64 zq[32];
    mlp_l12(grid[n], grid[NPTS + n], sw1, sb1, sw2q, sb2, zq);
    float4* op = (float4*)(g_sfeat + s * 64);
#pragma unroll 1
    for (int kg = 0; kg < 16; kg++) {
        float4 v4;
        MLP_L3_K(4 * kg + 0, v4.x);
        MLP_L3_K(4 * kg + 1, v4.y);
        MLP_L3_K(4 * kg + 2, v4.z);
        MLP_L3_K(4 * kg + 3, v4.w);
        op[kg] = v4;
    }
}

// ---------------- select: exact KGUAR-th largest of NSAMP samples per feature ----------------
__global__ __launch_bounds__(32) void k_select() {
    int f = blockIdx.x;
    int lane = threadIdx.x;
    unsigned keys[NSAMP / 32];
#pragma unroll
    for (int i = 0; i < NSAMP / 32; i++)
        keys[i] = okey(g_sfeat[(i * 32 + lane) * 64 + f]);

    unsigned T = 0u;
#pragma unroll
    for (int bit = 31; bit >= 0; bit--) {
        unsigned cand = T | (1u << bit);
        int c = 0;
#pragma unroll
        for (int i = 0; i < NSAMP / 32; i++) c += (keys[i] >= cand);
        c += __shfl_xor_sync(0xffffffffu, c, 16);
        c += __shfl_xor_sync(0xffffffffu, c, 8);
        c += __shfl_xor_sync(0xffffffffu, c, 4);
        c += __shfl_xor_sync(0xffffffffu, c, 2);
        c += __shfl_xor_sync(0xffffffffu, c, 1);
        if (c >= KGUAR) T = cand;
    }
    if (lane == 0) g_T[f] = dekey(T);
}

// ---------------- pack: one thread = one 32-point mask word ----------------
__global__ __launch_bounds__(256) void k_pack(const int* __restrict__ x) {
    __shared__ int sp[8];
    int tid = threadIdx.x;
    int w = blockIdx.x * 256 + tid;              // word id < NWORDTOT
    const int4* xp = (const int4*)x + (size_t)w * 8;
    unsigned word = 0;
#pragma unroll
    for (int i = 0; i < 8; i++) {
        int4 v = __ldg(xp + i);
        word |= (unsigned)(v.x == 1) << (4 * i + 0);
        word |= (unsigned)(v.y == 1) << (4 * i + 1);
        word |= (unsigned)(v.z == 1) << (4 * i + 2);
        word |= (unsigned)(v.w == 1) << (4 * i + 3);
    }
    int ch = w >> 11, wic = w & 2047;            // 2048 words/ch; 8 blocks per channel
    g_maskT[wic * NCH + ch] = word;

    int pc = __popc(word);
#pragma unroll
    for (int off = 16; off; off >>= 1)
        pc += __shfl_xor_sync(0xffffffffu, pc, off);
    if ((tid & 31) == 0) sp[tid >> 5] = pc;
    __syncthreads();
    if (tid == 0) {
        int tot = 0;
#pragma unroll
        for (int i = 0; i < 8; i++) tot += sp[i];
        atomicAdd(&g_popcnt[ch], tot);
    }
}

// ---------------- collect: full MLP, streamed layer-3 + threshold + feats store ----------------
__global__ __launch_bounds__(128) void k_collect(
    const float* __restrict__ grid,
    const float* __restrict__ w1, const float* __restrict__ b1,
    const float* __restrict__ w2, const float* __restrict__ b2,
    const float* __restrict__ w3, const float* __restrict__ b3)
{
    __shared__ float sw1[128], sb1[64], sb2[64], sb3[64], sT[64];
    __shared__ u64 sw2q[2048], sw3q[2048];
    int tid = threadIdx.x;
    load_mlp_smem(w1, b1, w2, b2, w3, b3, sw1, sb1, sw2q, sb2, sw3q, sb3, tid, 128);
    if (tid < 64) sT[tid] = g_T[tid];
    __syncthreads();

    int n = blockIdx.x * 128 + tid;
    u64 zq[32];
    mlp_l12(grid[n], grid[NPTS + n], sw1, sb1, sw2q, sb2, zq);

    float4* op = (float4*)(g_feats + (size_t)n * 64);
#pragma unroll 1
    for (int kg = 0; kg < 16; kg++) {
        float4 v4;
        MLP_L3_K(4 * kg + 0, v4.x);
        MLP_L3_K(4 * kg + 1, v4.y);
        MLP_L3_K(4 * kg + 2, v4.z);
        MLP_L3_K(4 * kg + 3, v4.w);
        op[kg] = v4;
#pragma unroll
        for (int q = 0; q < 4; q++) {
            int k = 4 * kg + q;
            float v = (q == 0) ? v4.x : (q == 1) ? v4.y : (q == 2) ? v4.z : v4.w;
            if (v >= sT[k]) {
                int p = atomicAdd(&g_cnt[k], 1);
                g_cand[(size_t)k * CAP + p] = make_int2(n, __float_as_int(v));
            }
        }
    }
}

// ---------------- query: smem-staged candidates, 8 slices x 128 ch ----------------
__global__ __launch_bounds__(1024) void k_query() {
    __shared__ int2 scand[QCHUNK];               // 16KB
    __shared__ float sred[8][128];
    __shared__ unsigned char sfnd[8][128];
    __shared__ int s_nfb;
    __shared__ unsigned char sflag[NCH];
    __shared__ float sfb[1024];

    int tid = threadIdx.x;
    int ch = tid & 127;           // active < 76
    int sl = tid >> 7;            // 8 slices
    int f = blockIdx.x;
    int cnt = g_cnt[f];

    if (tid == 0) s_nfb = 0;
    if (tid < NCH) sflag[tid] = 0;

    float m = -1e30f;
    bool found = false;
    for (int base = 0; base < cnt; base += QCHUNK) {
        int len = min(QCHUNK, cnt - base);
        __syncthreads();
        for (int i = tid; i < len; i += 1024)
            scand[i] = __ldg(g_cand + (size_t)f * CAP + base + i);
        __syncthreads();
        if (ch < NCH) {
            int per = (len + 7) >> 3;
            int i0 = sl * per, i1 = min(len, i0 + per);
            int i = i0;
            for (; i + 4 <= i1; i += 4) {
                int2 c0 = scand[i], c1 = scand[i + 1], c2 = scand[i + 2], c3 = scand[i + 3];
                unsigned w0 = __ldg(&g_maskT[(c0.x >> 5) * NCH + ch]);
                unsigned w1 = __ldg(&g_maskT[(c1.x >> 5) * NCH + ch]);
                unsigned w2 = __ldg(&g_maskT[(c2.x >> 5) * NCH + ch]);
                unsigned w3 = __ldg(&g_maskT[(c3.x >> 5) * NCH + ch]);
                if ((w0 >> (c0.x & 31)) & 1) { m = fmaxf(m, __int_as_float(c0.y)); found = true; }
                if ((w1 >> (c1.x & 31)) & 1) { m = fmaxf(m, __int_as_float(c1.y)); found = true; }
                if ((w2 >> (c2.x & 31)) & 1) { m = fmaxf(m, __int_as_float(c2.y)); found = true; }
                if ((w3 >> (c3.x & 31)) & 1) { m = fmaxf(m, __int_as_float(c3.y)); found = true; }
            }
            for (; i < i1; i++) {
                int2 c = scand[i];
                unsigned w = __ldg(&g_maskT[(c.x >> 5) * NCH + ch]);
                if ((w >> (c.x & 31)) & 1) { m = fmaxf(m, __int_as_float(c.y)); found = true; }
            }
        }
    }
    sred[sl][ch] = m;
    sfnd[sl][ch] = found;
    __syncthreads();

    if (tid < NCH) {
        float mm = -1e30f;
        int ff = 0;
#pragma unroll
        for (int s = 0; s < 8; s++) { mm = fmaxf(mm, sred[s][tid]); ff |= sfnd[s][tid]; }
        if (g_popcnt[tid] > 0) {
            if (ff) g_zres[tid * 64 + f] = mm;
            else { sflag[tid] = 1; atomicAdd(&s_nfb, 1); }
        }
    }
    __syncthreads();
    if (s_nfb == 0) return;

    // exact fallback (P ~ 2^-512 per pair): dense scan of stored feature column
    for (int c = 0; c < NCH; c++) {
        if (!sflag[c]) continue;
        float fm = -1e30f;
        for (int base = 0; base < NPTS; base += 1024) {
            int n = base + tid;
            float v = __ldg(&g_feats[(size_t)n * 64 + f]);
            unsigned w = g_maskT[(n >> 5) * NCH + c];
            if ((w >> (n & 31)) & 1) fm = fmaxf(fm, v);
        }
        sfb[tid] = fm;
        __syncthreads();
        for (int off = 512; off; off >>= 1) {
            if (tid < off) sfb[tid] = fmaxf(sfb[tid], sfb[tid + off]);
            __syncthreads();
        }
        if (tid == 0) g_zres[c * 64 + f] = sfb[0];
        __syncthreads();
    }
}

// ---------------- final FC + repeat 18 ----------------
__global__ __launch_bounds__(128) void k_fc(const float* __restrict__ fcw,
                                            const float* __restrict__ fcb,
                                            float* __restrict__ out)
{
    __shared__ float fs[NCH * NF];
    __shared__ float rw[4][4];

    int tid = threadIdx.x;
    int o = blockIdx.x;
    for (int i = tid; i < NCH * NF; i += 128) {
        int ch = i >> 6;
        fs[i] = (g_popcnt[ch] > 0) ? g_zres[i] : g_zf[i & 63];
    }
    __syncthreads();

    float p0 = 0.f, p1 = 0.f, p2 = 0.f, p3 = 0.f;
    const float* wr = fcw + o * 1216;
    for (int k = tid; k < 1216; k += 128) {
        float w = wr[k];
        p0 += w * fs[k];
        p1 += w * fs[1216 + k];
        p2 += w * fs[2432 + k];
        p3 += w * fs[3648 + k];
    }
#pragma unroll
    for (int off = 16; off; off >>= 1) {
        p0 += __shfl_xor_sync(0xffffffffu, p0, off);
        p1 += __shfl_xor_sync(0xffffffffu, p1, off);
        p2 += __shfl_xor_sync(0xffffffffu, p2, off);
        p3 += __shfl_xor_sync(0xffffffffu, p3, off);
    }
    int lane = tid & 31, wp = tid >> 5;
    if (lane == 0) { rw[wp][0] = p0; rw[wp][1] = p1; rw[wp][2] = p2; rw[wp][3] = p3; }
    __syncthreads();
    if (tid < 4) {
        float s = rw[0][tid] + rw[1][tid] + rw[2][tid] + rw[3][tid];
        float scale = rsqrtf(1216.0f);
        float val = s * scale + fcb[o];
#pragma unroll
        for (int r = 0; r < 18; r++)
            out[(tid * 18 + r) * 512 + o] = val;
    }
}

extern "C" void kernel_launch(void* const* d_in, const int* in_sizes, int n_in,
                              void* d_out, int out_size) {
    const int*   x    = (const int*)d_in[0];
    const float* grid = (const float*)d_in[1];
    const float* w1   = (const float*)d_in[2];
    const float* b1   = (const float*)d_in[3];
    const float* w2   = (const float*)d_in[4];
    const float* b2   = (const float*)d_in[5];
    const float* w3   = (const float*)d_in[6];
    const float* b3   = (const float*)d_in[7];
    const float* fcw  = (const float*)d_in[8];
    const float* fcb  = (const float*)d_in[9];
    float* out = (float*)d_out;

    k_prep<<<NSAMP / 128 + 1, 128>>>(grid, w1, b1, w2, b2, w3, b3);
    k_select<<<NF, 32>>>();
    k_pack<<<NWORDTOT / 256, 256>>>(x);
    k_collect<<<NPTS / 128, 128>>>(grid, w1, b1, w2, b2, w3, b3);
    k_query<<<NF, 1024>>>();
    k_fc<<<512, 128>>>(fcw, fcb, out);
}